// round 15
// baseline (speedup 1.0000x reference)
#include <cuda_runtime.h>
#include <cuda_fp16.h>
#include <cstdint>

#define S_DIM 2048
#define B_DIM 256
#define D_DIM 128
#define M_TOTAL (S_DIM * B_DIM)     // 524288 token rows
#define BD 32768                    // B*D scan lanes
#define SM1 2047
#define NJ 74                       // chain chunks (49x28 + 25x27)
#define ROWB 272                    // smem row stride bytes (136 halves)
#define TILEB (128 * ROWB)          // 34816 bytes per 128x128 fp16 tile

// Scratch
__device__ __half g_h[(size_t)M_TOTAL * 128];      // 134 MB : h fp16
__device__ __half g_uloc[(size_t)SM1 * BD];        // 134 MB : local cumsum fp16
__device__ float  g_tot[NJ * 32768];               // per-chunk sums
__device__ float  g_ptot[NJ * 32768];              // exclusive prefixes

__device__ __forceinline__ uint32_t s2u(const void* p) {
    uint32_t a;
    asm("{ .reg .u64 t; cvta.to.shared.u64 t, %1; cvt.u32.u64 %0, t; }"
        : "=r"(a) : "l"(p));
    return a;
}

__device__ __forceinline__ uint32_t packh2(float a, float b) {
    __half2 h = __floats2half2_rn(a, b);
    return *(uint32_t*)&h;
}

#define LDSM4(r0, r1, r2, r3, addr)                                            \
    asm volatile("ldmatrix.sync.aligned.m8n8.x4.shared.b16 {%0,%1,%2,%3}, [%4];" \
                 : "=r"(r0), "=r"(r1), "=r"(r2), "=r"(r3) : "r"(addr))

#define MMA_F16(acc, a, b)                                                     \
    asm volatile("mma.sync.aligned.m16n8k16.row.col.f32.f16.f16.f32 "          \
                 "{%0,%1,%2,%3}, {%4,%5,%6,%7}, {%8,%9}, {%0,%1,%2,%3};"       \
                 : "+f"((acc)[0]), "+f"((acc)[1]), "+f"((acc)[2]), "+f"((acc)[3]) \
                 : "r"((a)[0]), "r"((a)[1]), "r"((a)[2]), "r"((a)[3]),         \
                   "r"((b)[0]), "r"((b)[1]))

// ---------------------------------------------------------------------------
// 128x128 @ 128x128 accumulation pass (A smem, W smem [n][k] fp16).
// Warp grid 4(M)x2(N): mb=(w&3)*32, nb=(w>>2)*64.
// ---------------------------------------------------------------------------
__device__ __forceinline__ void gemm_phase(uint32_t aBase, uint32_t bBase,
                                           int mb, int nb, int lane,
                                           float (&acc)[2][8][4])
{
    const uint32_t arow = aBase + (uint32_t)(mb + (lane & 15)) * ROWB
                        + (uint32_t)((lane >> 4) * 16);
    uint32_t brow[4];
#pragma unroll
    for (int q = 0; q < 4; q++)
        brow[q] = bBase
                + (uint32_t)(nb + q * 16 + ((lane & 7) | ((lane >> 4) << 3))) * ROWB
                + (uint32_t)(((lane >> 3) & 1) * 16);

#pragma unroll
    for (int ks = 0; ks < 8; ks++) {
        const uint32_t ko = ks * 32;
        uint32_t a0[4], a1[4];
        LDSM4(a0[0], a0[1], a0[2], a0[3], arow + ko);
        LDSM4(a1[0], a1[1], a1[2], a1[3], arow + 16 * ROWB + ko);
        uint32_t bf[8][2];
#pragma unroll
        for (int q = 0; q < 4; q++) {
            uint32_t m0, m1, m2, m3;
            LDSM4(m0, m1, m2, m3, brow[q] + ko);
            bf[2 * q][0] = m0; bf[2 * q][1] = m1;
            bf[2 * q + 1][0] = m2; bf[2 * q + 1][1] = m3;
        }
#pragma unroll
        for (int nt = 0; nt < 8; nt++) {
            MMA_F16(acc[0][nt], a0, bf[nt]);
            MMA_F16(acc[1][nt], a1, bf[nt]);
        }
    }
}

// Stage a 128x128 fp32 tile -> fp16 chunks in regs (8 x uint4 per thread).
__device__ __forceinline__ void stage_cvt(const float* __restrict__ base,
                                          int tid, uint4* st) {
#pragma unroll
    for (int i = 0; i < 8; i++) {
        int c = i * 256 + tid;
        int row = c >> 4, col16 = c & 15;
        const float4* p = (const float4*)(base + row * 128 + col16 * 8);
        float4 f0 = p[0], f1 = p[1];
        uint4 v;
        v.x = packh2(f0.x, f0.y); v.y = packh2(f0.z, f0.w);
        v.z = packh2(f1.x, f1.y); v.w = packh2(f1.z, f1.w);
        st[i] = v;
    }
}

__device__ __forceinline__ void stage_cpy(const __half* __restrict__ base,
                                          int tid, uint4* st) {
#pragma unroll
    for (int i = 0; i < 8; i++) {
        int c = i * 256 + tid;
        int row = c >> 4, col16 = c & 15;
        st[i] = *(const uint4*)(base + row * 128 + col16 * 8);
    }
}

__device__ __forceinline__ void sts_stage(char* sA, int tid, const uint4* st) {
#pragma unroll
    for (int i = 0; i < 8; i++) {
        int c = i * 256 + tid;
        int row = c >> 4, col16 = c & 15;
        *(uint4*)(sA + row * ROWB + col16 * 16) = st[i];
    }
}

// Load W[k][n] fp32 (128x128) -> smem [n][k] fp16 (transposed).
__device__ __forceinline__ void load_w(const float* __restrict__ W, char* sW, int tid) {
    for (int idx = tid; idx < 16384; idx += 256) {
        int k = idx >> 7, n = idx & 127;
        *(__half*)(sW + n * ROWB + k * 2) = __float2half_rn(W[idx]);
    }
}

// ---------------------------------------------------------------------------
// Persistent map GEMM: h = relu(src @ Wm + bm) -> fp16. 128-row tiles.
// ONE sync per iteration; explicit sync after prologue (bias visibility).
// ---------------------------------------------------------------------------
__global__ void __launch_bounds__(256, 1)
gemm_map(const float* __restrict__ A, const float* __restrict__ W,
         const float* __restrict__ bias, __half* __restrict__ H)
{
    extern __shared__ char smem[];
    float* sbias = (float*)smem;
    char* sW  = smem + 512;
    char* sA0 = sW + TILEB;
    char* sA1 = sA0 + TILEB;

    const int tid = threadIdx.x;
    const int lane = tid & 31, w = tid >> 5;
    const int mb = (w & 3) * 32, nb = (w >> 2) * 64;
    const int grp = lane >> 2, thr = lane & 3;
    const int bid = blockIdx.x;
    const int base = bid * 27 + (bid < 100 ? bid : 100);
    const int cnt  = 27 + (bid < 100 ? 1 : 0);

    load_w(W, sW, tid);
    if (tid < 128) sbias[tid] = bias[tid];
    {
        uint4 st[8];
        stage_cvt(A + (size_t)base * 16384, tid, st);
        sts_stage(sA0, tid, st);
    }
    __syncthreads();   // prologue visibility: sbias/W/sA0 before any reads

    float br[8][2];
#pragma unroll
    for (int nt = 0; nt < 8; nt++) {
        int c = nb + nt * 8 + 2 * thr;
        br[nt][0] = sbias[c]; br[nt][1] = sbias[c + 1];
    }

    const uint32_t sWu = s2u(sW), sA0u = s2u(sA0), sA1u = s2u(sA1);
    char* sAb[2] = { sA0, sA1 };
    int cur = 0;
    for (int it = 0; it < cnt; it++) {
        const bool pref = (it + 1 < cnt);
        uint4 st[8];
        if (pref) stage_cvt(A + (size_t)(base + it + 1) * 16384, tid, st);

        float acc[2][8][4];
#pragma unroll
        for (int mt = 0; mt < 2; mt++)
#pragma unroll
            for (int nt = 0; nt < 8; nt++)
#pragma unroll
                for (int q = 0; q < 4; q++) acc[mt][nt][q] = 0.f;

        gemm_phase(cur ? sA1u : sA0u, sWu, mb, nb, lane, acc);

        if (pref) sts_stage(sAb[cur ^ 1], tid, st);   // target last read in it-1

        const size_t row0 = (size_t)(base + it) * 128;
#pragma unroll
        for (int mt = 0; mt < 2; mt++) {
#pragma unroll
            for (int nt = 0; nt < 8; nt++) {
                int r = mb + mt * 16 + grp;
                int c = nb + nt * 8 + 2 * thr;
                uint32_t v0 = packh2(fmaxf(acc[mt][nt][0] + br[nt][0], 0.f),
                                     fmaxf(acc[mt][nt][1] + br[nt][1], 0.f));
                uint32_t v1 = packh2(fmaxf(acc[mt][nt][2] + br[nt][0], 0.f),
                                     fmaxf(acc[mt][nt][3] + br[nt][1], 0.f));
                *(uint32_t*)(H + (row0 + r) * 128 + c) = v0;
                *(uint32_t*)(H + (row0 + r + 8) * 128 + c) = v1;
            }
        }
        cur ^= 1;
        __syncthreads();   // boundary: reads of old buf done + new STS visible
    }
}

// ---------------------------------------------------------------------------
// Persistent fused bracket + local cumsum. 128-row tiles (b-half), 3 A bufs.
//   u[s] = h[s] + relu(h[s]@Wb1 + h[s+1]@Wb2 + bb); uloc = fp16 running sum.
// ONE sync per iteration; explicit sync after prologue.
// ---------------------------------------------------------------------------
__global__ void __launch_bounds__(256, 1)
gemm_bracket(const __half* __restrict__ H, const float* __restrict__ Wb,
             const float* __restrict__ bb, __half* __restrict__ uloc,
             float* __restrict__ tot)
{
    extern __shared__ char smem[];
    float* sbias = (float*)smem;
    char* sW1 = smem + 512;
    char* sW2 = sW1 + TILEB;
    char* b0 = sW2 + TILEB;
    char* b1 = b0 + TILEB;
    char* b2 = b1 + TILEB;

    const int tid = threadIdx.x;
    const int lane = tid & 31, w = tid >> 5;
    const int mb = (w & 3) * 32, nb = (w >> 2) * 64;
    const int grp = lane >> 2, thr = lane & 3;
    const int bid = blockIdx.x;
    const int res = bid & 1;
    const int j   = bid >> 1;                       // 0..73
    const int i0  = j * 27 + (j < 49 ? j : 49);
    const int cnt = 27 + (j < 49 ? 1 : 0);

    load_w(Wb, sW1, tid);
    load_w(Wb + 16384, sW2, tid);
    if (tid < 128) sbias[tid] = bb[tid];

    const size_t t0 = (size_t)res + 2 * (size_t)i0;
    {
        uint4 st[8];
        stage_cpy(H + t0 * 16384, tid, st);
        sts_stage(b0, tid, st);
        stage_cpy(H + (t0 + 2) * 16384, tid, st);
        sts_stage(b1, tid, st);
    }
    __syncthreads();   // prologue visibility: sbias/W1/W2/b0/b1 before reads

    float br[8][2];
#pragma unroll
    for (int nt = 0; nt < 8; nt++) {
        int c = nb + nt * 8 + 2 * thr;
        br[nt][0] = sbias[c]; br[nt][1] = sbias[c + 1];
    }

    const uint32_t sW1u = s2u(sW1), sW2u = s2u(sW2);
    char* bt  = b0;   // holds h[s]
    char* bt2 = b1;   // holds h[s+1]
    char* bpr = b2;   // prefetch dest

    float racc[2][8][4];
#pragma unroll
    for (int mt = 0; mt < 2; mt++)
#pragma unroll
        for (int nt = 0; nt < 8; nt++)
#pragma unroll
            for (int q = 0; q < 4; q++) racc[mt][nt][q] = 0.f;

    for (int it = 0; it < cnt; it++) {
        const size_t t = (size_t)res + 2 * (size_t)(i0 + it);
        const bool pref = (it + 1 < cnt);
        uint4 st[8];
        if (pref) stage_cpy(H + (t + 4) * 16384, tid, st);

        float acc[2][8][4];
#pragma unroll
        for (int mt = 0; mt < 2; mt++)
#pragma unroll
            for (int nt = 0; nt < 8; nt++)
#pragma unroll
                for (int q = 0; q < 4; q++) acc[mt][nt][q] = 0.f;

        gemm_phase(s2u(bt),  sW1u, mb, nb, lane, acc);   // h[s]   @ Wb1
        if (pref) sts_stage(bpr, tid, st);               // bpr last read in it-1
        gemm_phase(s2u(bt2), sW2u, mb, nb, lane, acc);   // h[s+1] @ Wb2

        // epilogue: racc += h + relu(acc + bb); uloc = fp16(racc)
        const size_t obase = (size_t)(i0 + it) * BD + (size_t)res * 16384;
#pragma unroll
        for (int mt = 0; mt < 2; mt++) {
#pragma unroll
            for (int nt = 0; nt < 8; nt++) {
                int r = mb + mt * 16 + grp;
                int c = nb + nt * 8 + 2 * thr;
                float2 h0 = __half22float2(*(__half2*)(bt + r * ROWB + c * 2));
                float2 h1 = __half22float2(*(__half2*)(bt + (r + 8) * ROWB + c * 2));
                racc[mt][nt][0] += h0.x + fmaxf(acc[mt][nt][0] + br[nt][0], 0.f);
                racc[mt][nt][1] += h0.y + fmaxf(acc[mt][nt][1] + br[nt][1], 0.f);
                racc[mt][nt][2] += h1.x + fmaxf(acc[mt][nt][2] + br[nt][0], 0.f);
                racc[mt][nt][3] += h1.y + fmaxf(acc[mt][nt][3] + br[nt][1], 0.f);
                *(uint32_t*)(uloc + obase + r * 128 + c) =
                    packh2(racc[mt][nt][0], racc[mt][nt][1]);
                *(uint32_t*)(uloc + obase + (r + 8) * 128 + c) =
                    packh2(racc[mt][nt][2], racc[mt][nt][3]);
            }
        }

        char* tmp = bt; bt = bt2; bt2 = bpr; bpr = tmp;
        __syncthreads();   // boundary: old-buffer reads done + STS visible
    }

    // chain totals (fp32, exact racc)
    float* tbase = tot + (size_t)j * 32768 + (size_t)res * 16384;
#pragma unroll
    for (int mt = 0; mt < 2; mt++) {
#pragma unroll
        for (int nt = 0; nt < 8; nt++) {
            int r = mb + mt * 16 + grp;
            int c = nb + nt * 8 + 2 * thr;
            *(float2*)(tbase + r * 128 + c) =
                make_float2(racc[mt][nt][0], racc[mt][nt][1]);
            *(float2*)(tbase + (r + 8) * 128 + c) =
                make_float2(racc[mt][nt][2], racc[mt][nt][3]);
        }
    }
}

// Exclusive prefix over the 74 chunk totals (per lane).
__global__ void scan_prefix(const float* __restrict__ tot, float* __restrict__ ptot)
{
    const int lane = blockIdx.x * 256 + threadIdx.x;
    float a = 0.f;
#pragma unroll 2
    for (int jj = 0; jj < NJ; jj++) {
        float v = tot[(size_t)jj * 32768 + lane];
        ptot[(size_t)jj * 32768 + lane] = a;
        a += v;
    }
}

// out[s,lane] = float(uloc[s,lane]) + ptot[chunk(s)][lane].
// R6 body verbatim: 1 uint4 group (8 lanes) per thread, linear mapping,
// plain loads/stores — empirically the fastest variant (65.3us).
__global__ void fixup(const __half* __restrict__ uloc,
                      const float* __restrict__ ptot,
                      float* __restrict__ out)
{
    const size_t g = (size_t)blockIdx.x * 256 + threadIdx.x;   // 8-lane group id
    const int s = (int)(g >> 12);                              // 4096 groups per s
    const int rem = (int)(g & 4095);
    const int jj = (s < 1372) ? (s / 28) : (49 + (s - 1372) / 27);

    uint4 u = ((const uint4*)(uloc + (size_t)s * BD))[rem];
    const float4* pp = (const float4*)(ptot + (size_t)jj * 32768) + rem * 2;
    float4 p0 = pp[0], p1 = pp[1];

    float2 a = __half22float2(*(__half2*)&u.x);
    float2 b = __half22float2(*(__half2*)&u.y);
    float2 c = __half22float2(*(__half2*)&u.z);
    float2 d = __half22float2(*(__half2*)&u.w);

    float4 o0 = make_float4(a.x + p0.x, a.y + p0.y, b.x + p0.z, b.y + p0.w);
    float4 o1 = make_float4(c.x + p1.x, c.y + p1.y, d.x + p1.z, d.y + p1.w);

    float4* op = (float4*)(out + (size_t)s * BD) + rem * 2;
    op[0] = o0;
    op[1] = o1;
}

extern "C" void kernel_launch(void* const* d_in, const int* in_sizes, int n_in,
                              void* d_out, int out_size)
{
    const float* src = (const float*)d_in[0];   // [S, B, D]
    const float* Wm  = (const float*)d_in[1];   // [D, D]
    const float* bm  = (const float*)d_in[2];   // [D]
    const float* Wb  = (const float*)d_in[3];   // [2D, D]
    const float* bb  = (const float*)d_in[4];   // [D]
    float* out = (float*)d_out;                 // [S-1, B, D]

    void *hp_v, *ul_v, *tp_v, *pp_v;
    cudaGetSymbolAddress(&hp_v, g_h);
    cudaGetSymbolAddress(&ul_v, g_uloc);
    cudaGetSymbolAddress(&tp_v, g_tot);
    cudaGetSymbolAddress(&pp_v, g_ptot);
    __half* hp = (__half*)hp_v;
    __half* ul = (__half*)ul_v;
    float* tp = (float*)tp_v;
    float* pp = (float*)pp_v;

    const int smem_map = 512 + 3 * TILEB;   // 104960
    const int smem_brk = 512 + 5 * TILEB;   // 174592
    cudaFuncSetAttribute((const void*)gemm_map,
                         cudaFuncAttributeMaxDynamicSharedMemorySize, smem_map);
    cudaFuncSetAttribute((const void*)gemm_bracket,
                         cudaFuncAttributeMaxDynamicSharedMemorySize, smem_brk);

    gemm_map<<<148, 256, smem_map>>>(src, Wm, bm, hp);
    gemm_bracket<<<148, 256, smem_brk>>>(hp, Wb, bb, ul, tp);
    scan_prefix<<<128, 256>>>(tp, pp);
    fixup<<<32752, 256>>>(ul, pp, out);     // 2047 * 4096 / 256
}

// round 16
// speedup vs baseline: 1.5104x; 1.5104x over previous
#include <cuda_runtime.h>
#include <cuda_fp16.h>
#include <cstdint>

#define S_DIM 2048
#define B_DIM 256
#define D_DIM 128
#define M_TOTAL (S_DIM * B_DIM)     // 524288 token rows
#define BD 32768                    // B*D scan lanes
#define SM1 2047
#define NJ 74                       // chain chunks per b-half (49x28 + 25x27)
#define ROWB 272                    // smem row stride in bytes (136 halves)
#define TILEB (128 * ROWB)          // 34816 bytes per 128x128 fp16 tile

// Scratch
__device__ __half g_h[(size_t)M_TOTAL * 128];      // 134 MB : h fp16
__device__ __half g_uloc[(size_t)SM1 * BD];        // 134 MB : local cumsum fp16
__device__ float  g_tot[NJ * 32768];               // per-chunk sums
__device__ float  g_ptot[NJ * 32768];              // exclusive prefixes

__device__ __forceinline__ uint32_t s2u(const void* p) {
    uint32_t a;
    asm("{ .reg .u64 t; cvta.to.shared.u64 t, %1; cvt.u32.u64 %0, t; }"
        : "=r"(a) : "l"(p));
    return a;
}

__device__ __forceinline__ uint32_t packh2(float a, float b) {
    __half2 h = __floats2half2_rn(a, b);
    return *(uint32_t*)&h;
}

#define LDSM4(r0, r1, r2, r3, addr)                                            \
    asm volatile("ldmatrix.sync.aligned.m8n8.x4.shared.b16 {%0,%1,%2,%3}, [%4];" \
                 : "=r"(r0), "=r"(r1), "=r"(r2), "=r"(r3) : "r"(addr))

#define MMA_F16(acc, a, b)                                                     \
    asm volatile("mma.sync.aligned.m16n8k16.row.col.f32.f16.f16.f32 "          \
                 "{%0,%1,%2,%3}, {%4,%5,%6,%7}, {%8,%9}, {%0,%1,%2,%3};"       \
                 : "+f"((acc)[0]), "+f"((acc)[1]), "+f"((acc)[2]), "+f"((acc)[3]) \
                 : "r"((a)[0]), "r"((a)[1]), "r"((a)[2]), "r"((a)[3]),         \
                   "r"((b)[0]), "r"((b)[1]))

// ---------------------------------------------------------------------------
// One 128x128 @ 128x128 accumulation pass (A smem, W smem [n][k] fp16).
// Warp grid 4(M)x2(N): mb=(w&3)*32, nb=(w>>2)*64.
// ---------------------------------------------------------------------------
__device__ __forceinline__ void gemm_phase(uint32_t aBase, uint32_t bBase,
                                           int mb, int nb, int lane,
                                           float (&acc)[2][8][4])
{
    const uint32_t arow = aBase + (uint32_t)(mb + (lane & 15)) * ROWB
                        + (uint32_t)((lane >> 4) * 16);
    uint32_t brow[4];
#pragma unroll
    for (int q = 0; q < 4; q++)
        brow[q] = bBase
                + (uint32_t)(nb + q * 16 + ((lane & 7) | ((lane >> 4) << 3))) * ROWB
                + (uint32_t)(((lane >> 3) & 1) * 16);

#pragma unroll
    for (int ks = 0; ks < 8; ks++) {
        const uint32_t ko = ks * 32;
        uint32_t a0[4], a1[4];
        LDSM4(a0[0], a0[1], a0[2], a0[3], arow + ko);
        LDSM4(a1[0], a1[1], a1[2], a1[3], arow + 16 * ROWB + ko);
        uint32_t bf[8][2];
#pragma unroll
        for (int q = 0; q < 4; q++) {
            uint32_t m0, m1, m2, m3;
            LDSM4(m0, m1, m2, m3, brow[q] + ko);
            bf[2 * q][0] = m0; bf[2 * q][1] = m1;
            bf[2 * q + 1][0] = m2; bf[2 * q + 1][1] = m3;
        }
#pragma unroll
        for (int nt = 0; nt < 8; nt++) {
            MMA_F16(acc[0][nt], a0, bf[nt]);
            MMA_F16(acc[1][nt], a1, bf[nt]);
        }
    }
}

// Stage a 128x128 fp32 tile -> fp16 chunks in regs (8 x uint4 per thread).
__device__ __forceinline__ void stage_cvt(const float* __restrict__ base,
                                          int tid, uint4* st) {
#pragma unroll
    for (int i = 0; i < 8; i++) {
        int c = i * 256 + tid;
        int row = c >> 4, col16 = c & 15;
        const float4* p = (const float4*)(base + row * 128 + col16 * 8);
        float4 f0 = p[0], f1 = p[1];
        uint4 v;
        v.x = packh2(f0.x, f0.y); v.y = packh2(f0.z, f0.w);
        v.z = packh2(f1.x, f1.y); v.w = packh2(f1.z, f1.w);
        st[i] = v;
    }
}

__device__ __forceinline__ void stage_cpy(const __half* __restrict__ base,
                                          int tid, uint4* st) {
#pragma unroll
    for (int i = 0; i < 8; i++) {
        int c = i * 256 + tid;
        int row = c >> 4, col16 = c & 15;
        st[i] = *(const uint4*)(base + row * 128 + col16 * 8);
    }
}

__device__ __forceinline__ void sts_stage(char* sA, int tid, const uint4* st) {
#pragma unroll
    for (int i = 0; i < 8; i++) {
        int c = i * 256 + tid;
        int row = c >> 4, col16 = c & 15;
        *(uint4*)(sA + row * ROWB + col16 * 16) = st[i];
    }
}

// Load W[k][n] fp32 (128x128) -> smem [n][k] fp16 (transposed).
__device__ __forceinline__ void load_w(const float* __restrict__ W, char* sW, int tid) {
    for (int idx = tid; idx < 16384; idx += 256) {
        int k = idx >> 7, n = idx & 127;
        *(__half*)(sW + n * ROWB + k * 2) = __float2half_rn(W[idx]);
    }
}

// ---------------------------------------------------------------------------
// Persistent map GEMM: h = relu(src @ Wm + bm) -> fp16
// ---------------------------------------------------------------------------
__global__ void __launch_bounds__(256, 1)
gemm_map(const float* __restrict__ A, const float* __restrict__ W,
         const float* __restrict__ bias, __half* __restrict__ H)
{
    extern __shared__ char smem[];
    float* sbias = (float*)smem;
    char* sW  = smem + 512;
    char* sA0 = sW + TILEB;
    char* sA1 = sA0 + TILEB;

    const int tid = threadIdx.x;
    const int lane = tid & 31, w = tid >> 5;
    const int mb = (w & 3) * 32, nb = (w >> 2) * 64;
    const int grp = lane >> 2, thr = lane & 3;
    const int bid = blockIdx.x;
    const int base = bid * 27 + (bid < 100 ? bid : 100);
    const int cnt  = 27 + (bid < 100 ? 1 : 0);

    load_w(W, sW, tid);
    if (tid < 128) sbias[tid] = bias[tid];
    {
        uint4 st[8];
        stage_cvt(A + (size_t)base * 16384, tid, st);
        sts_stage(sA0, tid, st);
    }
    __syncthreads();

    float br[8][2];
#pragma unroll
    for (int nt = 0; nt < 8; nt++) {
        int c = nb + nt * 8 + 2 * thr;
        br[nt][0] = sbias[c]; br[nt][1] = sbias[c + 1];
    }

    const uint32_t sWu = s2u(sW), sA0u = s2u(sA0), sA1u = s2u(sA1);
    int cur = 0;
    for (int it = 0; it < cnt; it++) {
        const bool pref = (it + 1 < cnt);
        uint4 st[8];
        if (pref) stage_cvt(A + (size_t)(base + it + 1) * 16384, tid, st);

        float acc[2][8][4];
#pragma unroll
        for (int mt = 0; mt < 2; mt++)
#pragma unroll
            for (int nt = 0; nt < 8; nt++)
#pragma unroll
                for (int q = 0; q < 4; q++) acc[mt][nt][q] = 0.f;

        gemm_phase(cur ? sA1u : sA0u, sWu, mb, nb, lane, acc);

        const size_t row0 = (size_t)(base + it) * 128;
#pragma unroll
        for (int mt = 0; mt < 2; mt++) {
#pragma unroll
            for (int nt = 0; nt < 8; nt++) {
                int r = mb + mt * 16 + grp;
                int c = nb + nt * 8 + 2 * thr;
                uint32_t v0 = packh2(fmaxf(acc[mt][nt][0] + br[nt][0], 0.f),
                                     fmaxf(acc[mt][nt][1] + br[nt][1], 0.f));
                uint32_t v1 = packh2(fmaxf(acc[mt][nt][2] + br[nt][0], 0.f),
                                     fmaxf(acc[mt][nt][3] + br[nt][1], 0.f));
                *(uint32_t*)(H + (row0 + r) * 128 + c) = v0;
                *(uint32_t*)(H + (row0 + r + 8) * 128 + c) = v1;
            }
        }

        __syncthreads();
        if (pref) sts_stage(cur ? (char*)sA0 : (char*)sA1, tid, st);
        __syncthreads();
        cur ^= 1;
    }
}

// ---------------------------------------------------------------------------
// Persistent fused bracket + local cumsum:
//   u[s] = h[s] + relu(h[s]@Wb1 + h[s+1]@Wb2 + bb)
//   uloc[s] = running fp16 cumsum within chain; chain totals -> g_tot (fp32).
// ---------------------------------------------------------------------------
__global__ void __launch_bounds__(256, 1)
gemm_bracket(const __half* __restrict__ H, const float* __restrict__ Wb,
             const float* __restrict__ bb, __half* __restrict__ uloc,
             float* __restrict__ tot)
{
    extern __shared__ char smem[];
    float* sbias = (float*)smem;
    char* sW1 = smem + 512;
    char* sW2 = sW1 + TILEB;
    char* b0 = sW2 + TILEB;
    char* b1 = b0 + TILEB;
    char* b2 = b1 + TILEB;

    const int tid = threadIdx.x;
    const int lane = tid & 31, w = tid >> 5;
    const int mb = (w & 3) * 32, nb = (w >> 2) * 64;
    const int grp = lane >> 2, thr = lane & 3;
    const int bid = blockIdx.x;
    const int res = bid & 1;
    const int j   = bid >> 1;                       // 0..73
    const int i0  = j * 27 + (j < 49 ? j : 49);
    const int cnt = 27 + (j < 49 ? 1 : 0);

    load_w(Wb, sW1, tid);
    load_w(Wb + 16384, sW2, tid);
    if (tid < 128) sbias[tid] = bb[tid];

    const size_t t0 = (size_t)res + 2 * (size_t)i0;
    {
        uint4 st[8];
        stage_cpy(H + t0 * 16384, tid, st);
        sts_stage(b0, tid, st);
        stage_cpy(H + (t0 + 2) * 16384, tid, st);
        sts_stage(b1, tid, st);
    }
    __syncthreads();

    float br[8][2];
#pragma unroll
    for (int nt = 0; nt < 8; nt++) {
        int c = nb + nt * 8 + 2 * thr;
        br[nt][0] = sbias[c]; br[nt][1] = sbias[c + 1];
    }

    const uint32_t sW1u = s2u(sW1), sW2u = s2u(sW2);
    char* bt  = b0;
    char* bt2 = b1;
    char* bpr = b2;

    float racc[2][8][4];
#pragma unroll
    for (int mt = 0; mt < 2; mt++)
#pragma unroll
        for (int nt = 0; nt < 8; nt++)
#pragma unroll
            for (int q = 0; q < 4; q++) racc[mt][nt][q] = 0.f;

    for (int it = 0; it < cnt; it++) {
        const size_t t = (size_t)res + 2 * (size_t)(i0 + it);
        const bool pref = (it + 1 < cnt);
        uint4 st[8];
        if (pref) stage_cpy(H + (t + 4) * 16384, tid, st);

        float acc[2][8][4];
#pragma unroll
        for (int mt = 0; mt < 2; mt++)
#pragma unroll
            for (int nt = 0; nt < 8; nt++)
#pragma unroll
                for (int q = 0; q < 4; q++) acc[mt][nt][q] = 0.f;

        gemm_phase(s2u(bt),  sW1u, mb, nb, lane, acc);   // h[s]   @ Wb1
        gemm_phase(s2u(bt2), sW2u, mb, nb, lane, acc);   // h[s+1] @ Wb2

        // epilogue: racc += h + relu(acc + bb); uloc = fp16(racc)
        const size_t obase = (size_t)(i0 + it) * BD + (size_t)res * 16384;
#pragma unroll
        for (int mt = 0; mt < 2; mt++) {
#pragma unroll
            for (int nt = 0; nt < 8; nt++) {
                int r = mb + mt * 16 + grp;
                int c = nb + nt * 8 + 2 * thr;
                float2 h0 = __half22float2(*(__half2*)(bt + r * ROWB + c * 2));
                float2 h1 = __half22float2(*(__half2*)(bt + (r + 8) * ROWB + c * 2));
                racc[mt][nt][0] += h0.x + fmaxf(acc[mt][nt][0] + br[nt][0], 0.f);
                racc[mt][nt][1] += h0.y + fmaxf(acc[mt][nt][1] + br[nt][1], 0.f);
                racc[mt][nt][2] += h1.x + fmaxf(acc[mt][nt][2] + br[nt][0], 0.f);
                racc[mt][nt][3] += h1.y + fmaxf(acc[mt][nt][3] + br[nt][1], 0.f);
                *(uint32_t*)(uloc + obase + r * 128 + c) =
                    packh2(racc[mt][nt][0], racc[mt][nt][1]);
                *(uint32_t*)(uloc + obase + (r + 8) * 128 + c) =
                    packh2(racc[mt][nt][2], racc[mt][nt][3]);
            }
        }

        __syncthreads();
        if (pref) sts_stage(bpr, tid, st);
        __syncthreads();
        char* tmp = bt; bt = bt2; bt2 = bpr; bpr = tmp;
    }

    // chain totals (fp32, exact racc)
    float* tbase = tot + (size_t)j * 32768 + (size_t)res * 16384;
#pragma unroll
    for (int mt = 0; mt < 2; mt++) {
#pragma unroll
        for (int nt = 0; nt < 8; nt++) {
            int r = mb + mt * 16 + grp;
            int c = nb + nt * 8 + 2 * thr;
            *(float2*)(tbase + r * 128 + c) =
                make_float2(racc[mt][nt][0], racc[mt][nt][1]);
            *(float2*)(tbase + (r + 8) * 128 + c) =
                make_float2(racc[mt][nt][2], racc[mt][nt][3]);
        }
    }
}

// Exclusive prefix over the 74 chunk totals (per lane).
__global__ void scan_prefix(const float* __restrict__ tot, float* __restrict__ ptot)
{
    const int lane = blockIdx.x * 256 + threadIdx.x;
    float a = 0.f;
#pragma unroll 2
    for (int jj = 0; jj < NJ; jj++) {
        float v = tot[(size_t)jj * 32768 + lane];
        ptot[(size_t)jj * 32768 + lane] = a;
        a += v;
    }
}

// out[s,lane] = float(uloc[s,lane]) + ptot[chunk(s)][lane]; 8 lanes per thread.
__global__ void fixup(const __half* __restrict__ uloc,
                      const float* __restrict__ ptot,
                      float* __restrict__ out)
{
    const size_t g = (size_t)blockIdx.x * 256 + threadIdx.x;   // 8-lane group id
    const int s = (int)(g >> 12);                              // 4096 groups per s
    const int rem = (int)(g & 4095);
    const int jj = (s < 1372) ? (s / 28) : (49 + (s - 1372) / 27);

    uint4 u = ((const uint4*)(uloc + (size_t)s * BD))[rem];
    const float4* pp = (const float4*)(ptot + (size_t)jj * 32768) + rem * 2;
    float4 p0 = pp[0], p1 = pp[1];

    float2 a = __half22float2(*(__half2*)&u.x);
    float2 b = __half22float2(*(__half2*)&u.y);
    float2 c = __half22float2(*(__half2*)&u.z);
    float2 d = __half22float2(*(__half2*)&u.w);

    float4 o0 = make_float4(a.x + p0.x, a.y + p0.y, b.x + p0.z, b.y + p0.w);
    float4 o1 = make_float4(c.x + p1.x, c.y + p1.y, d.x + p1.z, d.y + p1.w);

    float4* op = (float4*)(out + (size_t)s * BD) + rem * 2;
    op[0] = o0;
    op[1] = o1;
}

extern "C" void kernel_launch(void* const* d_in, const int* in_sizes, int n_in,
                              void* d_out, int out_size)
{
    const float* src = (const float*)d_in[0];   // [S, B, D]
    const float* Wm  = (const float*)d_in[1];   // [D, D]
    const float* bm  = (const float*)d_in[2];   // [D]
    const float* Wb  = (const float*)d_in[3];   // [2D, D]
    const float* bb  = (const float*)d_in[4];   // [D]
    float* out = (float*)d_out;                 // [S-1, B, D]

    void *hp_v, *ul_v, *tp_v, *pp_v;
    cudaGetSymbolAddress(&hp_v, g_h);
    cudaGetSymbolAddress(&ul_v, g_uloc);
    cudaGetSymbolAddress(&tp_v, g_tot);
    cudaGetSymbolAddress(&pp_v, g_ptot);
    __half* hp = (__half*)hp_v;
    __half* ul = (__half*)ul_v;
    float* tp = (float*)tp_v;
    float* pp = (float*)pp_v;

    const int smem_map = 512 + 3 * TILEB;   // 104960
    const int smem_brk = 512 + 5 * TILEB;   // 174592
    cudaFuncSetAttribute((const void*)gemm_map,
                         cudaFuncAttributeMaxDynamicSharedMemorySize, smem_map);
    cudaFuncSetAttribute((const void*)gemm_bracket,
                         cudaFuncAttributeMaxDynamicSharedMemorySize, smem_brk);

    gemm_map<<<148, 256, smem_map>>>(src, Wm, bm, hp);
    gemm_bracket<<<148, 256, smem_brk>>>(hp, Wb, bb, ul, tp);
    scan_prefix<<<128, 256>>>(tp, pp);
    fixup<<<32752, 256>>>(ul, pp, out);     // 2047 * 4096 / 256
}